// round 5
// baseline (speedup 1.0000x reference)
#include <cuda_runtime.h>

#define OBS_LEN 8
#define PRED_LEN 12
#define BATCHN 65536
#define HID 64
#define NG 256           // 4*HID gates
#define BLK 128

// Precomputed per-phase (0=encoder, 1=decoder) parameters:
//   g_cm[ph][0..255]    = Mx[j]  (input-x combined weight)
//   g_cm[ph][256..511]  = My[j]
//   g_cm[ph][512..767]  = CB[j]  = w_ih@emb_b + b_ih + b_hh
//   g_wT[ph][k*256 + j] = w_hh[j][k]  (transposed recurrent weights)
__device__ float g_cm[2][768];
__device__ float g_wT[2][HID * NG];

// ---------------------------------------------------------------------------
// f32x2 helpers (Blackwell packed fp32 FMA; ptxas never auto-fuses these)
// ---------------------------------------------------------------------------
__device__ __forceinline__ unsigned long long pack2(float x, float y) {
    unsigned long long r;
    asm("mov.b64 %0, {%1, %2};" : "=l"(r) : "f"(x), "f"(y));
    return r;
}
__device__ __forceinline__ void fma2(unsigned long long& d,
                                     unsigned long long a,
                                     unsigned long long b) {
    asm("fma.rn.f32x2 %0, %1, %2, %0;" : "+l"(d) : "l"(a), "l"(b));
}
__device__ __forceinline__ float2 unpack2(unsigned long long v) {
    float2 r;
    asm("mov.b64 {%0, %1}, %2;" : "=f"(r.x), "=f"(r.y) : "l"(v));
    return r;
}

// Fast activations (MUFU.EX2 + MUFU.RCP; rel err ~1e-6, well under 1e-3)
__device__ __forceinline__ float fsig(float x) {
    return __fdividef(1.0f, 1.0f + __expf(-x));
}
__device__ __forceinline__ float ftanh_(float x) {
    return 1.0f - 2.0f * __fdividef(1.0f, 1.0f + __expf(2.0f * x));
}

// ---------------------------------------------------------------------------
// Prep kernel: fold embedding into input-projection, transpose w_hh
// ---------------------------------------------------------------------------
__global__ void vlstm_prep(const float* __restrict__ ew, const float* __restrict__ eb,
                           const float* __restrict__ wih_e, const float* __restrict__ whh_e,
                           const float* __restrict__ bih_e, const float* __restrict__ bhh_e,
                           const float* __restrict__ dw, const float* __restrict__ db,
                           const float* __restrict__ wih_d, const float* __restrict__ whh_d,
                           const float* __restrict__ bih_d, const float* __restrict__ bhh_d)
{
    int j = threadIdx.x;  // 0..255 = gate row
    for (int ph = 0; ph < 2; ph++) {
        const float* emb_w = ph ? dw : ew;
        const float* emb_b = ph ? db : eb;
        const float* wih   = ph ? wih_d : wih_e;
        const float* whh   = ph ? whh_d : whh_e;
        const float* bih   = ph ? bih_d : bih_e;
        const float* bhh   = ph ? bhh_d : bhh_e;
        float mx = 0.f, my = 0.f, mb = 0.f;
        #pragma unroll 8
        for (int e = 0; e < 64; e++) {
            float wv = wih[j * 64 + e];
            mx += wv * emb_w[e * 2 + 0];
            my += wv * emb_w[e * 2 + 1];
            mb += wv * emb_b[e];
        }
        g_cm[ph][j]       = mx;
        g_cm[ph][256 + j] = my;
        g_cm[ph][512 + j] = mb + bih[j] + bhh[j];
        #pragma unroll 8
        for (int k = 0; k < 64; k++)
            g_wT[ph][k * NG + j] = whh[j * 64 + k];
    }
}

// ---------------------------------------------------------------------------
// One LSTM step for this thread's batch element.
// hcur/hnxt/cS are [64][BLK] shared columns (column tid is thread-private).
// Gates processed in 4 hidden-unit groups of 16 (i,f,g,o rows together) so
// the activation can run with only 32 f32x2 accumulators live.
// ---------------------------------------------------------------------------
template <bool DEC>
__device__ __forceinline__ void lstm_step(
    const float* __restrict__ sWT, const float* __restrict__ sCM,
    const float* __restrict__ hcur, float* __restrict__ hnxt,
    float* __restrict__ cS, int tid, float px, float py,
    const float* __restrict__ sP0, const float* __restrict__ sP1,
    float& rx, float& ry)
{
    const unsigned long long px2 = pack2(px, px);
    const unsigned long long py2 = pack2(py, py);

    #pragma unroll 1
    for (int grp = 0; grp < 4; grp++) {
        const int m = grp * 16;                 // hidden units m..m+15
        unsigned long long acc[32];             // [gate_type 4][pair 8]

        // init: combined bias + M * pos  (input-side contribution)
        #pragma unroll
        for (int gt = 0; gt < 4; gt++) {
            #pragma unroll
            for (int p = 0; p < 8; p++) {
                int j = gt * 64 + m + 2 * p;
                unsigned long long a = *(const unsigned long long*)(sCM + 512 + j);
                fma2(a, *(const unsigned long long*)(sCM + j),       px2);
                fma2(a, *(const unsigned long long*)(sCM + 256 + j), py2);
                acc[gt * 8 + p] = a;
            }
        }

        // recurrent matvec: gates += w_hh^T[k][...] * h[k]
        const float* hp = hcur + tid;
        #pragma unroll 4
        for (int k = 0; k < 64; k++) {
            float hk = hp[k * BLK];
            unsigned long long h2 = pack2(hk, hk);
            const float* wr = sWT + k * NG + m;
            #pragma unroll
            for (int gt = 0; gt < 4; gt++) {
                ulonglong2 w0 = *(const ulonglong2*)(wr + gt * 64);
                ulonglong2 w1 = *(const ulonglong2*)(wr + gt * 64 + 4);
                ulonglong2 w2 = *(const ulonglong2*)(wr + gt * 64 + 8);
                ulonglong2 w3 = *(const ulonglong2*)(wr + gt * 64 + 12);
                fma2(acc[gt * 8 + 0], w0.x, h2);
                fma2(acc[gt * 8 + 1], w0.y, h2);
                fma2(acc[gt * 8 + 2], w1.x, h2);
                fma2(acc[gt * 8 + 3], w1.y, h2);
                fma2(acc[gt * 8 + 4], w2.x, h2);
                fma2(acc[gt * 8 + 5], w2.y, h2);
                fma2(acc[gt * 8 + 6], w3.x, h2);
                fma2(acc[gt * 8 + 7], w3.y, h2);
            }
        }

        // activations + state update for units m..m+15
        #pragma unroll
        for (int p = 0; p < 8; p++) {
            float2 iv = unpack2(acc[0 * 8 + p]);
            float2 fv = unpack2(acc[1 * 8 + p]);
            float2 gv = unpack2(acc[2 * 8 + p]);
            float2 ov = unpack2(acc[3 * 8 + p]);
            int u = m + 2 * p;
            {
                float is = fsig(iv.x), fs = fsig(fv.x);
                float gg = ftanh_(gv.x), os = fsig(ov.x);
                float cn = fmaf(fs, cS[u * BLK + tid], is * gg);
                cS[u * BLK + tid] = cn;
                float hn = os * ftanh_(cn);
                hnxt[u * BLK + tid] = hn;
                if (DEC) { rx = fmaf(hn, sP0[u], rx); ry = fmaf(hn, sP1[u], ry); }
            }
            {
                float is = fsig(iv.y), fs = fsig(fv.y);
                float gg = ftanh_(gv.y), os = fsig(ov.y);
                float cn = fmaf(fs, cS[(u + 1) * BLK + tid], is * gg);
                cS[(u + 1) * BLK + tid] = cn;
                float hn = os * ftanh_(cn);
                hnxt[(u + 1) * BLK + tid] = hn;
                if (DEC) { rx = fmaf(hn, sP0[u + 1], rx); ry = fmaf(hn, sP1[u + 1], ry); }
            }
        }
    }
}

// Shared layout (floats):
//   [0,16384)       sWT  (current phase recurrent weights, transposed)
//   [16384,17152)   sCM  (Mx | My | CB)
//   [17152,17216)   sP0  (h2p row 0)
//   [17216,17280)   sP1  (h2p row 1)
//   [17280,+8192)   hA ; then hB ; then cS
#define SM_FLOATS (17280 + 3 * HID * BLK)

__global__ void __launch_bounds__(BLK, 1)
vlstm_main(const float* __restrict__ obs_rel,
           const float* __restrict__ h2p_w, const float* __restrict__ h2p_b,
           float* __restrict__ out)
{
    extern __shared__ float sm[];
    float* sWT = sm;
    float* sCM = sm + 16384;
    float* sP0 = sm + 17152;
    float* sP1 = sm + 17216;
    float* hA  = sm + 17280;
    float* hB  = hA + HID * BLK;
    float* cS  = hB + HID * BLK;

    const int tid = threadIdx.x;
    const int b   = blockIdx.x * BLK + tid;

    // ---- load encoder-phase weights + h2p ----
    {
        const float4* src = (const float4*)g_wT[0];
        float4* dst = (float4*)sWT;
        for (int i = tid; i < HID * NG / 4; i += BLK) dst[i] = src[i];
        for (int i = tid; i < 768; i += BLK) sCM[i] = g_cm[0][i];
        if (tid < 64) { sP0[tid] = h2p_w[tid]; sP1[tid] = h2p_w[64 + tid]; }
    }
    #pragma unroll
    for (int u = 0; u < HID; u++) { hA[u * BLK + tid] = 0.f; cS[u * BLK + tid] = 0.f; }
    __syncthreads();

    float dr0 = 0.f, dr1 = 0.f;
    const float* hc = hA;
    float* hn = hB;

    // ---- encoder: 8 steps ----
    #pragma unroll 1
    for (int t = 0; t < OBS_LEN; t++) {
        float2 pos = *(const float2*)(obs_rel + (size_t)(t * BATCHN + b) * 2);
        lstm_step<false>(sWT, sCM, hc, hn, cS, tid, pos.x, pos.y, sP0, sP1, dr0, dr1);
        float* tmp = hn; hn = (float*)hc; hc = tmp;
    }

    // ---- swap in decoder-phase weights ----
    __syncthreads();
    {
        const float4* src = (const float4*)g_wT[1];
        float4* dst = (float4*)sWT;
        for (int i = tid; i < HID * NG / 4; i += BLK) dst[i] = src[i];
        for (int i = tid; i < 768; i += BLK) sCM[i] = g_cm[1][i];
    }
    #pragma unroll
    for (int u = 0; u < HID; u++) cS[u * BLK + tid] = 0.f;   // decoder c0 = 0
    __syncthreads();

    const float pb0 = h2p_b[0], pb1 = h2p_b[1];
    float2 rel = *(const float2*)(obs_rel + (size_t)(7 * BATCHN + b) * 2);

    // ---- decoder: 12 steps, autoregressive through h2p ----
    #pragma unroll 1
    for (int t = 0; t < PRED_LEN; t++) {
        float rx = pb0, ry = pb1;
        lstm_step<true>(sWT, sCM, hc, hn, cS, tid, rel.x, rel.y, sP0, sP1, rx, ry);
        float* tmp = hn; hn = (float*)hc; hc = tmp;
        rel.x = rx; rel.y = ry;
        *(float2*)(out + (size_t)(t * BATCHN + b) * 2) = rel;
    }
}

// ---------------------------------------------------------------------------
// Launch
// ---------------------------------------------------------------------------
extern "C" void kernel_launch(void* const* d_in, const int* in_sizes, int n_in,
                              void* d_out, int out_size)
{
    // metadata order: 0 obs_traj(unused), 1 obs_traj_rel,
    // 2..7 enc{emb_w,emb_b,w_ih,w_hh,b_ih,b_hh}, 8..13 dec{...}, 14 h2p_w, 15 h2p_b
    const float* obs_rel = (const float*)d_in[1];

    vlstm_prep<<<1, 256>>>(
        (const float*)d_in[2],  (const float*)d_in[3],
        (const float*)d_in[4],  (const float*)d_in[5],
        (const float*)d_in[6],  (const float*)d_in[7],
        (const float*)d_in[8],  (const float*)d_in[9],
        (const float*)d_in[10], (const float*)d_in[11],
        (const float*)d_in[12], (const float*)d_in[13]);

    const size_t smem = (size_t)SM_FLOATS * sizeof(float);   // ~167 KB
    cudaFuncSetAttribute(vlstm_main, cudaFuncAttributeMaxDynamicSharedMemorySize, (int)smem);
    vlstm_main<<<BATCHN / BLK, BLK, smem>>>(
        obs_rel, (const float*)d_in[14], (const float*)d_in[15], (float*)d_out);
}

// round 6
// speedup vs baseline: 1.4813x; 1.4813x over previous
#include <cuda_runtime.h>

#define OBS_LEN 8
#define PRED_LEN 12
#define BATCHN 65536
#define HID 64
#define NG 256           // 4*HID gates
#define BLK 128          // threads per block
#define EPB 256          // batch elements per block (2 per thread)

// Precomputed per-phase (0=encoder, 1=decoder) parameters:
//   g_cm[ph][0..255]    = Mx[j]   (input-x combined weight)
//   g_cm[ph][256..511]  = My[j]
//   g_cm[ph][512..767]  = CB[j]   = w_ih@emb_b + b_ih + b_hh
//   g_wT[ph][k*256 + j] = w_hh[j][k]  (transposed recurrent weights)
__device__ float g_cm[2][768];
__device__ float g_wT[2][HID * NG];
// c-state scratch: [unit][batch], thread-private columns, L2-resident (16 MB)
__device__ float g_cS[HID * BATCHN];

// ---------------------------------------------------------------------------
// f32x2 helpers (Blackwell packed fp32 FMA)
// ---------------------------------------------------------------------------
__device__ __forceinline__ unsigned long long pack2(float x, float y) {
    unsigned long long r;
    asm("mov.b64 %0, {%1, %2};" : "=l"(r) : "f"(x), "f"(y));
    return r;
}
__device__ __forceinline__ void fma2(unsigned long long& d,
                                     unsigned long long a,
                                     unsigned long long b) {
    asm("fma.rn.f32x2 %0, %1, %2, %0;" : "+l"(d) : "l"(a), "l"(b));
}
__device__ __forceinline__ float2 unpack2(unsigned long long v) {
    float2 r;
    asm("mov.b64 {%0, %1}, %2;" : "=f"(r.x), "=f"(r.y) : "l"(v));
    return r;
}

// Fast activations (MUFU; rel err ~1e-6)
__device__ __forceinline__ float fsig(float x) {
    return __fdividef(1.0f, 1.0f + __expf(-x));
}
__device__ __forceinline__ float ftanh_(float x) {
    return 1.0f - 2.0f * __fdividef(1.0f, 1.0f + __expf(2.0f * x));
}

// ---------------------------------------------------------------------------
// Prep kernel: fold embedding into input-projection, transpose w_hh
// ---------------------------------------------------------------------------
__global__ void vlstm_prep(const float* __restrict__ ew, const float* __restrict__ eb,
                           const float* __restrict__ wih_e, const float* __restrict__ whh_e,
                           const float* __restrict__ bih_e, const float* __restrict__ bhh_e,
                           const float* __restrict__ dw, const float* __restrict__ db,
                           const float* __restrict__ wih_d, const float* __restrict__ whh_d,
                           const float* __restrict__ bih_d, const float* __restrict__ bhh_d)
{
    int j = threadIdx.x;  // 0..255 = gate row
    for (int ph = 0; ph < 2; ph++) {
        const float* emb_w = ph ? dw : ew;
        const float* emb_b = ph ? db : eb;
        const float* wih   = ph ? wih_d : wih_e;
        const float* whh   = ph ? whh_d : whh_e;
        const float* bih   = ph ? bih_d : bih_e;
        const float* bhh   = ph ? bhh_d : bhh_e;
        float mx = 0.f, my = 0.f, mb = 0.f;
        #pragma unroll 8
        for (int e = 0; e < 64; e++) {
            float wv = wih[j * 64 + e];
            mx += wv * emb_w[e * 2 + 0];
            my += wv * emb_w[e * 2 + 1];
            mb += wv * emb_b[e];
        }
        g_cm[ph][j]       = mx;
        g_cm[ph][256 + j] = my;
        g_cm[ph][512 + j] = mb + bih[j] + bhh[j];
        #pragma unroll 8
        for (int k = 0; k < 64; k++)
            g_wT[ph][k * NG + j] = whh[j * 64 + k];
    }
}

// ---------------------------------------------------------------------------
// One LSTM step for this thread's TWO batch elements (A = e0, B = e0+1).
// Gates processed in 8 groups of 8 hidden units (acc = 32 u64 = 64 regs).
// c lives in global scratch (cG = &g_cS[b0]), prefetched per group.
// ---------------------------------------------------------------------------
template <bool DEC>
__device__ __forceinline__ void lstm_step2(
    const float* __restrict__ sWT, const float* __restrict__ sCM,
    const float* __restrict__ hcur, float* __restrict__ hnxt,
    float* __restrict__ cG, int e0,
    float pxA, float pyA, float pxB, float pyB,
    const float* __restrict__ sP0, const float* __restrict__ sP1,
    float& rxA, float& ryA, float& rxB, float& ryB)
{
    const unsigned long long pxA2 = pack2(pxA, pxA);
    const unsigned long long pyA2 = pack2(pyA, pyA);
    const unsigned long long pxB2 = pack2(pxB, pxB);
    const unsigned long long pyB2 = pack2(pyB, pyB);

    #pragma unroll 1
    for (int grp = 0; grp < 8; grp++) {
        const int m = grp * 8;   // hidden units m..m+7

        // Prefetch c for this group's 8 units (global/L2; latency hidden by matvec)
        float2 cpre[8];
        #pragma unroll
        for (int i = 0; i < 8; i++)
            cpre[i] = *(const float2*)(cG + (m + i) * BATCHN);

        // init accumulators: CB + M * pos
        unsigned long long aA[16], aB[16];  // [gate_type 4][pair 4]
        #pragma unroll
        for (int gt = 0; gt < 4; gt++) {
            #pragma unroll
            for (int p = 0; p < 4; p++) {
                int j = gt * 64 + m + 2 * p;
                unsigned long long mx = *(const unsigned long long*)(sCM + j);
                unsigned long long my = *(const unsigned long long*)(sCM + 256 + j);
                unsigned long long cb = *(const unsigned long long*)(sCM + 512 + j);
                unsigned long long tA = cb, tB = cb;
                fma2(tA, mx, pxA2); fma2(tA, my, pyA2);
                fma2(tB, mx, pxB2); fma2(tB, my, pyB2);
                aA[gt * 4 + p] = tA;
                aB[gt * 4 + p] = tB;
            }
        }

        // recurrent matvec: each weight LDS.128 feeds 4 FFMA2 (2 elements)
        const float* hp = hcur + e0;
        #pragma unroll 4
        for (int k = 0; k < 64; k++) {
            float2 hv = *(const float2*)(hp + k * EPB);       // h[k] for A,B
            unsigned long long h2A = pack2(hv.x, hv.x);
            unsigned long long h2B = pack2(hv.y, hv.y);
            const float* wr = sWT + k * NG + m;
            #pragma unroll
            for (int gt = 0; gt < 4; gt++) {
                ulonglong2 w01 = *(const ulonglong2*)(wr + gt * 64);
                ulonglong2 w23 = *(const ulonglong2*)(wr + gt * 64 + 4);
                fma2(aA[gt * 4 + 0], w01.x, h2A); fma2(aB[gt * 4 + 0], w01.x, h2B);
                fma2(aA[gt * 4 + 1], w01.y, h2A); fma2(aB[gt * 4 + 1], w01.y, h2B);
                fma2(aA[gt * 4 + 2], w23.x, h2A); fma2(aB[gt * 4 + 2], w23.x, h2B);
                fma2(aA[gt * 4 + 3], w23.y, h2A); fma2(aB[gt * 4 + 3], w23.y, h2B);
            }
        }

        // activations + state update for units m..m+7, both elements
        #pragma unroll
        for (int p = 0; p < 4; p++) {
            float2 iA = unpack2(aA[0  + p]), iB = unpack2(aB[0  + p]);
            float2 fA = unpack2(aA[4  + p]), fB = unpack2(aB[4  + p]);
            float2 gA = unpack2(aA[8  + p]), gB = unpack2(aB[8  + p]);
            float2 oA = unpack2(aA[12 + p]), oB = unpack2(aB[12 + p]);
            int u = m + 2 * p;
            {   // unit u  (x lanes)
                float2 cv = cpre[2 * p];
                float cnA = fmaf(fsig(fA.x), cv.x, fsig(iA.x) * ftanh_(gA.x));
                float cnB = fmaf(fsig(fB.x), cv.y, fsig(iB.x) * ftanh_(gB.x));
                *(float2*)(cG + u * BATCHN) = make_float2(cnA, cnB);
                float hnA = fsig(oA.x) * ftanh_(cnA);
                float hnB = fsig(oB.x) * ftanh_(cnB);
                *(float2*)(hnxt + u * EPB + e0) = make_float2(hnA, hnB);
                if (DEC) {
                    rxA = fmaf(hnA, sP0[u], rxA); ryA = fmaf(hnA, sP1[u], ryA);
                    rxB = fmaf(hnB, sP0[u], rxB); ryB = fmaf(hnB, sP1[u], ryB);
                }
            }
            {   // unit u+1 (y lanes)
                float2 cv = cpre[2 * p + 1];
                float cnA = fmaf(fsig(fA.y), cv.x, fsig(iA.y) * ftanh_(gA.y));
                float cnB = fmaf(fsig(fB.y), cv.y, fsig(iB.y) * ftanh_(gB.y));
                *(float2*)(cG + (u + 1) * BATCHN) = make_float2(cnA, cnB);
                float hnA = fsig(oA.y) * ftanh_(cnA);
                float hnB = fsig(oB.y) * ftanh_(cnB);
                *(float2*)(hnxt + (u + 1) * EPB + e0) = make_float2(hnA, hnB);
                if (DEC) {
                    rxA = fmaf(hnA, sP0[u + 1], rxA); ryA = fmaf(hnA, sP1[u + 1], ryA);
                    rxB = fmaf(hnB, sP0[u + 1], rxB); ryB = fmaf(hnB, sP1[u + 1], ryB);
                }
            }
        }
    }
}

// Shared layout (floats):
//   [0,16384)       sWT  (current phase recurrent weights, transposed)
//   [16384,17152)   sCM  (Mx | My | CB)
//   [17152,17216)   sP0 ; [17216,17280) sP1 ; pad to 17408
//   [17408,+16384)  hA ; then hB
#define SM_FLOATS (17408 + 2 * HID * EPB)   // 50176 floats = 200704 B

__global__ void __launch_bounds__(BLK, 1)
vlstm_main(const float* __restrict__ obs_rel,
           const float* __restrict__ h2p_w, const float* __restrict__ h2p_b,
           float* __restrict__ out)
{
    extern __shared__ float sm[];
    float* sWT = sm;
    float* sCM = sm + 16384;
    float* sP0 = sm + 17152;
    float* sP1 = sm + 17216;
    float* hA  = sm + 17408;
    float* hB  = hA + HID * EPB;

    const int tid = threadIdx.x;
    const int e0  = 2 * tid;                       // local element pair
    const int b0  = blockIdx.x * EPB + e0;         // global element pair
    float* cG = g_cS + b0;

    // ---- load encoder-phase weights + cm + h2p ----
    {
        const float4* src = (const float4*)g_wT[0];
        float4* dst = (float4*)sWT;
        for (int i = tid; i < HID * NG / 4; i += BLK) dst[i] = src[i];
        for (int i = tid; i < 768; i += BLK) sCM[i] = g_cm[0][i];
        if (tid < 64) { sP0[tid] = h2p_w[tid]; sP1[tid] = h2p_w[64 + tid]; }
    }
    #pragma unroll
    for (int u = 0; u < HID; u++) {
        *(float2*)(hA + u * EPB + e0)   = make_float2(0.f, 0.f);
        *(float2*)(cG + u * BATCHN)     = make_float2(0.f, 0.f);
    }
    __syncthreads();

    float dum = 0.f;
    float* hc = hA;
    float* hn = hB;

    // ---- encoder: 8 steps ----
    #pragma unroll 1
    for (int t = 0; t < OBS_LEN; t++) {
        float4 pos = *(const float4*)(obs_rel + (size_t)(t * BATCHN + b0) * 2);
        lstm_step2<false>(sWT, sCM, hc, hn, cG, e0,
                          pos.x, pos.y, pos.z, pos.w,
                          sP0, sP1, dum, dum, dum, dum);
        float* tmp = hn; hn = hc; hc = tmp;
    }

    // ---- swap in decoder-phase weights, reset c ----
    __syncthreads();
    {
        const float4* src = (const float4*)g_wT[1];
        float4* dst = (float4*)sWT;
        for (int i = tid; i < HID * NG / 4; i += BLK) dst[i] = src[i];
        for (int i = tid; i < 768; i += BLK) sCM[i] = g_cm[1][i];
    }
    #pragma unroll
    for (int u = 0; u < HID; u++)
        *(float2*)(cG + u * BATCHN) = make_float2(0.f, 0.f);
    __syncthreads();

    const float pb0 = h2p_b[0], pb1 = h2p_b[1];
    float4 rel = *(const float4*)(obs_rel + (size_t)(7 * BATCHN + b0) * 2);

    // ---- decoder: 12 steps, autoregressive through h2p ----
    #pragma unroll 1
    for (int t = 0; t < PRED_LEN; t++) {
        float rxA = pb0, ryA = pb1, rxB = pb0, ryB = pb1;
        lstm_step2<true>(sWT, sCM, hc, hn, cG, e0,
                         rel.x, rel.y, rel.z, rel.w,
                         sP0, sP1, rxA, ryA, rxB, ryB);
        float* tmp = hn; hn = hc; hc = tmp;
        rel = make_float4(rxA, ryA, rxB, ryB);
        *(float4*)(out + (size_t)(t * BATCHN + b0) * 2) = rel;
    }
}

// ---------------------------------------------------------------------------
// Launch
// ---------------------------------------------------------------------------
extern "C" void kernel_launch(void* const* d_in, const int* in_sizes, int n_in,
                              void* d_out, int out_size)
{
    // metadata order: 0 obs_traj(unused), 1 obs_traj_rel,
    // 2..7 enc{emb_w,emb_b,w_ih,w_hh,b_ih,b_hh}, 8..13 dec{...}, 14 h2p_w, 15 h2p_b
    const float* obs_rel = (const float*)d_in[1];

    vlstm_prep<<<1, 256>>>(
        (const float*)d_in[2],  (const float*)d_in[3],
        (const float*)d_in[4],  (const float*)d_in[5],
        (const float*)d_in[6],  (const float*)d_in[7],
        (const float*)d_in[8],  (const float*)d_in[9],
        (const float*)d_in[10], (const float*)d_in[11],
        (const float*)d_in[12], (const float*)d_in[13]);

    const size_t smem = (size_t)SM_FLOATS * sizeof(float);   // ~196 KB
    cudaFuncSetAttribute(vlstm_main, cudaFuncAttributeMaxDynamicSharedMemorySize, (int)smem);
    vlstm_main<<<BATCHN / EPB, BLK, smem>>>(
        obs_rel, (const float*)d_in[14], (const float*)d_in[15], (float*)d_out);
}